// round 5
// baseline (speedup 1.0000x reference)
#include <cuda_runtime.h>

// HausdorffDTLoss: B=4, C=2, H=W=256, ALPHA=2 — bit-exact vs the reference
// 2-pass brute-force squared EDT.
// Row pass stores packed u16 *distances* (fg in low16, bg in high16; the half
// not matching the pixel's own bit is exactly 0; sentinel d=1023 when a row
// has no opposite bit). Column pass does an exact integer min of d*d + r^2:
// finite sums < 2^18 (fp32-exact ints in the reference too), sentinel-involved
// sums >= 2^20 and only win when every row is sentinel, in which case the
// reference result is exactly 1e9 (its j=i term). Window r<=4 is exact when
// best <= 25 (any r>=5 candidate >= 25); otherwise a rare exact extension
// loop scans the full column from global memory.

#define NBLK 256

__device__ uint2 g_pack[4][256 * 256];
__device__ float g_partial[NBLK];
__device__ unsigned g_sync1;  // zero at load; reset by last block -> replay-safe
__device__ unsigned g_sync2;

// ---------------------------------------------------------------------------
// nearest opposite-valued bit in a 256-bit row mask
// ---------------------------------------------------------------------------
__device__ __forceinline__ int nearest_opp(const unsigned* __restrict__ w, int i,
                                           unsigned inv) {
    const int k = i >> 5, bpos = i & 31;
    unsigned m = (w[k] ^ inv) & (0xFFFFFFFFu >> (31 - bpos));
    int L = -1000000, kk = k;
    while (true) {
        if (m) { L = (kk << 5) + 31 - __clz(m); break; }
        if (--kk < 0) break;
        m = w[kk] ^ inv;
    }
    m = (w[k] ^ inv) & (0xFFFFFFFFu << bpos);
    int R = 1000000;
    kk = k;
    while (true) {
        if (m) { R = (kk << 5) + __ffs(m) - 1; break; }
        if (++kk > 7) break;
        m = w[kk] ^ inv;
    }
    return min(i - L, R - i);
}

// ---------------------------------------------------------------------------
// rare exact extension beyond the r<=4 window (global column scan)
// ---------------------------------------------------------------------------
__device__ __noinline__ unsigned extend(const uint2* __restrict__ src, int i,
                                        int col, int sh, int useY,
                                        unsigned best) {
#pragma unroll 1
    for (int r = 5; r < 256; ++r) {
        unsigned rr = (unsigned)(r * r);
        if (rr >= best) break;
        int lo = i - r, hi = i + r;
        if (lo >= 0) {
            uint2 w = __ldg(&src[lo * 256 + col]);
            unsigned d = ((useY ? w.y : w.x) >> sh) & 0xFFFFu;
            best = min(best, d * d + rr);
        }
        if (hi < 256) {
            uint2 w = __ldg(&src[hi * 256 + col]);
            unsigned d = ((useY ? w.y : w.x) >> sh) & 0xFFFFu;
            best = min(best, d * d + rr);
        }
    }
    return best;
}

// ---------------------------------------------------------------------------
// fused persistent kernel: row pass -> grid sync -> column pass + loss
// grid = 256 blocks x 256 threads (co-resident: 2 blocks/SM on 148 SMs)
// ---------------------------------------------------------------------------
__global__ __launch_bounds__(256) void k_fused(const float* __restrict__ mo,
                                               const float* __restrict__ gt,
                                               float* __restrict__ out) {
    const int bid = blockIdx.x;
    const int t = threadIdx.x;

    __shared__ unsigned P[8], G[8];
    __shared__ uint2 tile[40 * 8];  // 2.5 KB
    __shared__ float wsum[8];
    __shared__ bool last;

    // ---------------- phase 1: row pass (4 rows per block) ----------------
#pragma unroll 1
    for (int k = 0; k < 4; ++k) {
        int u = bid * 4 + k;  // 0..1023
        int b = u >> 8, r = u & 255;
        float m0 = mo[((b * 2 + 0) * 256 + r) * 256 + t];
        float m1 = mo[((b * 2 + 1) * 256 + r) * 256 + t];
        bool pb = (m1 > m0);  // argmax ties -> channel 0
        bool gb = (gt[(b * 256 + r) * 256 + t] > 0.5f);
        unsigned bp = __ballot_sync(0xFFFFFFFFu, pb);
        unsigned bg = __ballot_sync(0xFFFFFFFFu, gb);
        if ((t & 31) == 0) {
            P[t >> 5] = bp;
            G[t >> 5] = bg;
        }
        __syncthreads();
        int pd = nearest_opp(P, t, pb ? 0xFFFFFFFFu : 0u);
        int gd = nearest_opp(G, t, gb ? 0xFFFFFFFFu : 0u);
        unsigned ps = (pd > 255) ? 1023u : (unsigned)pd;
        unsigned gs = (gd > 255) ? 1023u : (unsigned)gd;
        uint2 o;
        o.x = pb ? ps : (ps << 16);  // fg dist low16, bg dist high16 (other = 0)
        o.y = gb ? gs : (gs << 16);
        g_pack[b][r * 256 + t] = o;
        __syncthreads();  // P/G reused next iteration
    }

    // ---------------- grid sync ----------------
    __threadfence();
    __syncthreads();
    if (t == 0) {
        atomicAdd(&g_sync1, 1u);
        while (*((volatile unsigned*)&g_sync1) < NBLK) __nanosleep(32);
    }
    __syncthreads();
    __threadfence();

    // ---------------- phase 2: column pass + loss (4 tiles per block) ------
    float acc = 0.0f;
#pragma unroll 1
    for (int k = 0; k < 4; ++k) {
        int tid2 = bid * 4 + k;  // 0..1023
        int b = tid2 >> 8, ry = (tid2 >> 5) & 7, cg = tid2 & 31;
        int base = ry * 32 - 4;
        const uint2* src = g_pack[b];

        {  // load 40x8 tile (halo rows = fake sentinel, never win)
            int trow = t >> 3, c2 = t & 7, grow = base + trow;
            tile[t] = ((unsigned)grow < 256u) ? src[grow * 256 + cg * 8 + c2]
                                              : make_uint2(0x03FF03FFu, 0x03FF03FFu);
            if (t < 64) {
                int idx2 = t + 256;
                int trow2 = idx2 >> 3, c22 = idx2 & 7, grow2 = base + trow2;
                tile[idx2] = ((unsigned)grow2 < 256u)
                                 ? src[grow2 * 256 + cg * 8 + c22]
                                 : make_uint2(0x03FF03FFu, 0x03FF03FFu);
            }
        }
        __syncthreads();

        int c = t & 7;
        int ti = (t >> 3) + 4;
        int i = ry * 32 + (t >> 3);
        int col = cg * 8 + c;
        const uint2* tcol = tile + c;

        uint2 v = tcol[ti * 8];
        bool pbit = (v.x & 0xFFFFu) != 0u;  // own-plane dist >= 1 iff own bit set
        bool gbit = (v.y & 0xFFFFu) != 0u;
        int shp = pbit ? 0 : 16;
        int shg = gbit ? 0 : 16;

        unsigned bestP = 0xFFFFFFFFu, bestG = 0xFFFFFFFFu;
#pragma unroll
        for (int dr = -4; dr <= 4; ++dr) {
            uint2 w = tcol[(ti + dr) * 8];
            unsigned rr = (unsigned)(dr * dr);
            unsigned dp = (w.x >> shp) & 0xFFFFu;
            unsigned dg = (w.y >> shg) & 0xFFFFu;
            bestP = min(bestP, dp * dp + rr);
            bestG = min(bestG, dg * dg + rr);
        }
        if (bestP > 25u) bestP = extend(src, i, col, shp, 0, bestP);
        if (bestG > 25u) bestG = extend(src, i, col, shg, 1, bestG);

        float e = (pbit != gbit) ? 1.0f : 0.0f;
        float Dp = (bestP >= (1u << 20)) ? 1.0e9f : (float)bestP;
        float sp = sqrtf(Dp);
        float pterm = sp * sp;  // fl(sqrt(D)^2): matches reference rounding
        if (!pbit && bestP >= (1u << 20)) pterm = 0.0f;  // fg-empty guard
        float Dg = (bestG >= (1u << 20)) ? 1.0e9f : (float)bestG;
        float sg = sqrtf(Dg);
        float gterm = sg * sg;
        if (!gbit && bestG >= (1u << 20)) gterm = 0.0f;
        acc += e * (pterm + gterm);

        __syncthreads();  // tile reused next iteration
    }

    // ---------------- block reduction + last-block finalize ----------------
#pragma unroll
    for (int o = 16; o > 0; o >>= 1) acc += __shfl_down_sync(0xFFFFFFFFu, acc, o);
    if ((t & 31) == 0) wsum[t >> 5] = acc;
    __syncthreads();
    if (t == 0) {
        float s = 0.0f;
#pragma unroll
        for (int j = 0; j < 8; ++j) s += wsum[j];
        g_partial[bid] = s;
        __threadfence();
        last = (atomicAdd(&g_sync2, 1u) == NBLK - 1);
    }
    __syncthreads();
    if (last) {
        __threadfence();
        float s = g_partial[t];
#pragma unroll
        for (int o = 16; o > 0; o >>= 1) s += __shfl_down_sync(0xFFFFFFFFu, s, o);
        if ((t & 31) == 0) wsum[t >> 5] = s;
        __syncthreads();
        if (t == 0) {
            float tot = 0.0f;
#pragma unroll
            for (int j = 0; j < 8; ++j) tot += wsum[j];
            out[0] = tot * (1.0f / 262144.0f);
            g_sync1 = 0;  // reset for next graph replay
            g_sync2 = 0;
        }
    }
}

extern "C" void kernel_launch(void* const* d_in, const int* in_sizes, int n_in,
                              void* d_out, int out_size) {
    const float* mo = (const float*)d_in[0];  // model_output (4,2,256,256) f32
    const float* gt = (const float*)d_in[1];  // ground_truth (4,1,256,256) f32
    float* out = (float*)d_out;

    k_fused<<<NBLK, 256>>>(mo, gt, out);
}